// round 10
// baseline (speedup 1.0000x reference)
#include <cuda_runtime.h>
#include <cstdint>

// Problem constants (fixed shapes per reference)
#define B_DIM 8
#define P_DIM 65536
#define C_DIM 32768
#define F_DIM 32
#define E_DIM 524288
#define THREADS 128
#define WARPS 4

// Per-channel edge-range offsets (edge_channel is sorted)
__device__ int g_offs[C_DIM + 1];

// ---------- packed f32x2 helpers ----------
__device__ __forceinline__ unsigned long long ffma2(unsigned long long a,
                                                    unsigned long long b,
                                                    unsigned long long c) {
    unsigned long long d;
    asm("fma.rn.f32x2 %0, %1, %2, %3;" : "=l"(d) : "l"(a), "l"(b), "l"(c));
    return d;
}
__device__ __forceinline__ unsigned long long add2(unsigned long long a,
                                                   unsigned long long b) {
    unsigned long long d;
    asm("add.rn.f32x2 %0, %1, %2;" : "=l"(d) : "l"(a), "l"(b));
    return d;
}
__device__ __forceinline__ float hadd2(unsigned long long v) {
    float lo, hi;
    asm("mov.b64 {%0, %1}, %2;" : "=f"(lo), "=f"(hi) : "l"(v));
    return lo + hi;
}
__device__ __forceinline__ float fast_rcp(float x) {
    float r;
    asm("rcp.approx.f32 %0, %1;" : "=f"(r) : "f"(x));
    return r;
}
__device__ __forceinline__ float sigmoidf_fast(float x) {
    return fast_rcp(1.0f + __expf(-x));
}
__device__ __forceinline__ float tanhf_fast(float x) {
    return fmaf(2.0f, sigmoidf_fast(2.0f * x), -1.0f);
}

// ---------- kernel 1: segment offsets via binary search ----------
__global__ void offsets_kernel(const int* __restrict__ ec) {
    int c = blockIdx.x * blockDim.x + threadIdx.x;
    if (c > C_DIM) return;
    int lo = 0, hi = E_DIM;
    while (lo < hi) {
        int mid = (lo + hi) >> 1;
        if (ec[mid] < c) lo = mid + 1; else hi = mid;
    }
    g_offs[c] = lo;  // lower_bound(edge_channel, c); c == C_DIM -> E_DIM
}

// ---------- kernel 2: fused gather + GRU (two-pass gates) ----------
// 128-thread CTA (4 warps), one warp per channel. launch_bounds(128,5)
// targets ~96 regs -> 5 CTAs = 20 warps/SM without spilling (R8 spilled at
// the 80-reg cap; R7 ran 16 warps at 128 regs).
// Gather phase: lane = (bb = lane>>3, q8 = lane&7); each 128B path row is
// covered by exactly one LDG.128. GEMM: lane = output feature j; pass A
// computes r,z gates, pass B the n gate (halved live accumulators).
__global__ __launch_bounds__(THREADS, 5)
void gru_kernel(const float* __restrict__ pf,   // path_features   [B,P,F]
                const float* __restrict__ hf,   // channel_features[B,C,F]
                const float* __restrict__ Wih,  // [3F,F]
                const float* __restrict__ Whh,  // [3F,F]
                const float* __restrict__ bih,  // [3F]
                const float* __restrict__ bhh,  // [3F]
                const int*   __restrict__ ep,   // edge_path [E]
                float*       __restrict__ out)  // [B,C,F]
{
    // Weights as float4 quads: sW[fq][row] = W[row][4fq .. 4fq+3]
    __shared__ float4 sWih[8 * 96];
    __shared__ float4 sWhh[8 * 96];
    __shared__ float  sBias[128];
    // Per-warp staging: x (agg) and h, layout [b][f]
    __shared__ __align__(16) float sA[WARPS][256];
    __shared__ __align__(16) float sH[WARPS][256];

    const int tid = threadIdx.x;

    for (int i = tid; i < 8 * 96; i += THREADS) {
        int fq = i / 96, row = i % 96;
        sWih[i] = __ldg((const float4*)(Wih + row * 32 + fq * 4));
        sWhh[i] = __ldg((const float4*)(Whh + row * 32 + fq * 4));
    }
    if (tid < 32) {
        sBias[tid]      = bih[tid]      + bhh[tid];       // r bias (combined)
        sBias[32 + tid] = bih[32 + tid] + bhh[32 + tid];  // z bias (combined)
        sBias[64 + tid] = bih[64 + tid];                  // n input bias
        sBias[96 + tid] = bhh[64 + tid];                  // n hidden bias (inside r*)
    }
    __syncthreads();

    const int w = tid >> 5, lane = tid & 31;
    const int c   = blockIdx.x * WARPS + w;
    const int bb  = lane >> 3;       // batch 0..3 (and bb+4 for second half)
    const int q8  = lane & 7;        // feature quad 0..7

    // ---- gather: two float4 accumulators (batch bb and batch bb+4) ----
    unsigned long long aA0 = 0ull, aA1 = 0ull;   // batch bb,   feats q8*4..+4
    unsigned long long aB0 = 0ull, aB1 = 0ull;   // batch bb+4, feats q8*4..+4
    const float* pfA = pf + (size_t)bb * (P_DIM * F_DIM) + q8 * 4;
    const float* pfB = pfA + (size_t)4 * (P_DIM * F_DIM);

    const int s0 = g_offs[c], e0 = g_offs[c + 1];
    int i = s0;
    for (; i + 4 <= e0; i += 4) {
        int p0 = __ldg(ep + i + 0);
        int p1 = __ldg(ep + i + 1);
        int p2 = __ldg(ep + i + 2);
        int p3 = __ldg(ep + i + 3);
        ulonglong2 vA0 = *(const ulonglong2*)(pfA + ((size_t)p0 << 5));
        ulonglong2 vB0 = *(const ulonglong2*)(pfB + ((size_t)p0 << 5));
        ulonglong2 vA1 = *(const ulonglong2*)(pfA + ((size_t)p1 << 5));
        ulonglong2 vB1 = *(const ulonglong2*)(pfB + ((size_t)p1 << 5));
        ulonglong2 vA2 = *(const ulonglong2*)(pfA + ((size_t)p2 << 5));
        ulonglong2 vB2 = *(const ulonglong2*)(pfB + ((size_t)p2 << 5));
        ulonglong2 vA3 = *(const ulonglong2*)(pfA + ((size_t)p3 << 5));
        ulonglong2 vB3 = *(const ulonglong2*)(pfB + ((size_t)p3 << 5));
        aA0 = add2(aA0, vA0.x); aA1 = add2(aA1, vA0.y);
        aB0 = add2(aB0, vB0.x); aB1 = add2(aB1, vB0.y);
        aA0 = add2(aA0, vA1.x); aA1 = add2(aA1, vA1.y);
        aB0 = add2(aB0, vB1.x); aB1 = add2(aB1, vB1.y);
        aA0 = add2(aA0, vA2.x); aA1 = add2(aA1, vA2.y);
        aB0 = add2(aB0, vB2.x); aB1 = add2(aB1, vB2.y);
        aA0 = add2(aA0, vA3.x); aA1 = add2(aA1, vA3.y);
        aB0 = add2(aB0, vB3.x); aB1 = add2(aB1, vB3.y);
    }
    for (; i < e0; i++) {
        int p = __ldg(ep + i);
        ulonglong2 vA = *(const ulonglong2*)(pfA + ((size_t)p << 5));
        ulonglong2 vB = *(const ulonglong2*)(pfB + ((size_t)p << 5));
        aA0 = add2(aA0, vA.x); aA1 = add2(aA1, vA.y);
        aB0 = add2(aB0, vB.x); aB1 = add2(aB1, vB.y);
    }

    // ---- stage x and h into per-warp shared (vector STS, conflict-free) ----
    {
        ulonglong2 accA; accA.x = aA0; accA.y = aA1;
        ulonglong2 accB; accB.x = aB0; accB.y = aB1;
        *(ulonglong2*)&sA[w][bb * 32 + q8 * 4]       = accA;
        *(ulonglong2*)&sA[w][(bb + 4) * 32 + q8 * 4] = accB;
        const float* hA = hf + (size_t)bb * (C_DIM * F_DIM) + ((size_t)c << 5) + q8 * 4;
        const float* hB = hA + (size_t)4 * (C_DIM * F_DIM);
        ulonglong2 hvA = *(const ulonglong2*)hA;   // coalesced 128B per batch row
        ulonglong2 hvB = *(const ulonglong2*)hB;
        *(ulonglong2*)&sH[w][bb * 32 + q8 * 4]       = hvA;
        *(ulonglong2*)&sH[w][(bb + 4) * 32 + q8 * 4] = hvB;
    }
    __syncwarp();

    const ulonglong2* WI = (const ulonglong2*)sWih;
    const ulonglong2* WH = (const ulonglong2*)sWhh;

    // ---- pass A: r and z gates (16 u64 accumulators) ----
    float r[B_DIM], z[B_DIM];
    {
        unsigned long long accr[B_DIM], accz[B_DIM];
#pragma unroll
        for (int b = 0; b < B_DIM; b++) { accr[b] = 0ull; accz[b] = 0ull; }

#pragma unroll
        for (int fq = 0; fq < 8; fq++) {
            ulonglong2 wir = WI[fq * 96 + lane];        // conflict-free LDS.128
            ulonglong2 wiz = WI[fq * 96 + 32 + lane];
            ulonglong2 whr = WH[fq * 96 + lane];
            ulonglong2 whz = WH[fq * 96 + 32 + lane];
#pragma unroll
            for (int b = 0; b < B_DIM; b++) {
                ulonglong2 a = *(const ulonglong2*)&sA[w][b * 32 + fq * 4];  // broadcast
                ulonglong2 h = *(const ulonglong2*)&sH[w][b * 32 + fq * 4];  // broadcast
                accr[b] = ffma2(a.y, wir.y, ffma2(a.x, wir.x, accr[b]));
                accr[b] = ffma2(h.y, whr.y, ffma2(h.x, whr.x, accr[b]));
                accz[b] = ffma2(a.y, wiz.y, ffma2(a.x, wiz.x, accz[b]));
                accz[b] = ffma2(h.y, whz.y, ffma2(h.x, whz.x, accz[b]));
            }
        }
        const float br = sBias[lane];
        const float bz = sBias[32 + lane];
#pragma unroll
        for (int b = 0; b < B_DIM; b++) {
            r[b] = sigmoidf_fast(hadd2(accr[b]) + br);
            z[b] = sigmoidf_fast(hadd2(accz[b]) + bz);
        }
    }

    // ---- pass B: n gate (16 u64 accumulators, reusing pass-A registers) ----
    {
        unsigned long long accxn[B_DIM], acchn[B_DIM];
#pragma unroll
        for (int b = 0; b < B_DIM; b++) { accxn[b] = 0ull; acchn[b] = 0ull; }

#pragma unroll
        for (int fq = 0; fq < 8; fq++) {
            ulonglong2 win = WI[fq * 96 + 64 + lane];
            ulonglong2 whn = WH[fq * 96 + 64 + lane];
#pragma unroll
            for (int b = 0; b < B_DIM; b++) {
                ulonglong2 a = *(const ulonglong2*)&sA[w][b * 32 + fq * 4];  // broadcast
                ulonglong2 h = *(const ulonglong2*)&sH[w][b * 32 + fq * 4];  // broadcast
                accxn[b] = ffma2(a.y, win.y, ffma2(a.x, win.x, accxn[b]));
                acchn[b] = ffma2(h.y, whn.y, ffma2(h.x, whn.x, acchn[b]));
            }
        }

        const float bxn = sBias[64 + lane];
        const float bhn = sBias[96 + lane];
        float* outp = out + ((size_t)c << 5) + lane;
#pragma unroll
        for (int b = 0; b < B_DIM; b++) {
            float n  = tanhf_fast(hadd2(accxn[b]) + bxn + r[b] * (hadd2(acchn[b]) + bhn));
            float hv = sH[w][b * 32 + lane];
            outp[(size_t)b * (C_DIM * F_DIM)] = (1.0f - z[b]) * n + z[b] * hv;  // coalesced STG
        }
    }
}

extern "C" void kernel_launch(void* const* d_in, const int* in_sizes, int n_in,
                              void* d_out, int out_size) {
    (void)in_sizes; (void)n_in; (void)out_size;
    const float* pf  = (const float*)d_in[0];
    const float* hf  = (const float*)d_in[1];
    const float* Wih = (const float*)d_in[2];
    const float* Whh = (const float*)d_in[3];
    const float* bih = (const float*)d_in[4];
    const float* bhh = (const float*)d_in[5];
    const int*   ep  = (const int*)d_in[6];
    const int*   ec  = (const int*)d_in[7];
    float* out = (float*)d_out;

    offsets_kernel<<<(C_DIM + 1 + 255) / 256, 256>>>(ec);
    gru_kernel<<<C_DIM / WARPS, THREADS>>>(pf, hf, Wih, Whh, bih, bhh, ep, out);
}

// round 12
// speedup vs baseline: 3.4976x; 3.4976x over previous
#include <cuda_runtime.h>
#include <cstdint>

// Problem constants (fixed shapes per reference)
#define B_DIM 8
#define P_DIM 65536
#define C_DIM 32768
#define F_DIM 32
#define E_DIM 524288
#define THREADS 256
#define CH_PER_CTA 8

// Per-channel edge-range offsets (edge_channel is sorted)
__device__ int g_offs[C_DIM + 1];

// ---------- packed f32x2 helpers ----------
__device__ __forceinline__ unsigned long long ffma2(unsigned long long a,
                                                    unsigned long long b,
                                                    unsigned long long c) {
    unsigned long long d;
    asm("fma.rn.f32x2 %0, %1, %2, %3;" : "=l"(d) : "l"(a), "l"(b), "l"(c));
    return d;
}
__device__ __forceinline__ unsigned long long add2(unsigned long long a,
                                                   unsigned long long b) {
    unsigned long long d;
    asm("add.rn.f32x2 %0, %1, %2;" : "=l"(d) : "l"(a), "l"(b));
    return d;
}
__device__ __forceinline__ float hadd2(unsigned long long v) {
    float lo, hi;
    asm("mov.b64 {%0, %1}, %2;" : "=f"(lo), "=f"(hi) : "l"(v));
    return lo + hi;
}
__device__ __forceinline__ float fast_rcp(float x) {
    float r;
    asm("rcp.approx.f32 %0, %1;" : "=f"(r) : "f"(x));
    return r;
}
__device__ __forceinline__ float sigmoidf_fast(float x) {
    return fast_rcp(1.0f + __expf(-x));
}
__device__ __forceinline__ float tanhf_fast(float x) {
    return fmaf(2.0f, sigmoidf_fast(2.0f * x), -1.0f);
}

// ---------- kernel 1: segment offsets via binary search ----------
__global__ void offsets_kernel(const int* __restrict__ ec) {
    int c = blockIdx.x * blockDim.x + threadIdx.x;
    if (c > C_DIM) return;
    int lo = 0, hi = E_DIM;
    while (lo < hi) {
        int mid = (lo + hi) >> 1;
        if (ec[mid] < c) lo = mid + 1; else hi = mid;
    }
    g_offs[c] = lo;  // lower_bound(edge_channel, c); c == C_DIM -> E_DIM
}

// ---------- kernel 2: fused gather + GRU (warp-pair, 2 channels/warp) ----------
// CTA = 256 threads = 8 warps = 4 warp-pairs, 8 channels per CTA.
// Warp w: pair p = w>>1 owns channels {2p, 2p+1}; parity = w&1 selects
// batches [parity*4, parity*4+4). Each warp gathers + GEMMs BOTH channels
// for its 4 batches: weight LDS amortized over 2 channels (192 -> 96
// wavefronts/channel) with accumulator count unchanged (2ch x 4b x 4 gates
// = 32 u64, same as R7's 1ch x 8b).
// Gather lane map: bb = lane>>3 (batch within half), q8 = lane&7 (feature
// quad): one LDG.128 per edge covers 4 batch rows x 128B exactly.
__global__ __launch_bounds__(THREADS, 2)
void gru_kernel(const float* __restrict__ pf,   // path_features   [B,P,F]
                const float* __restrict__ hf,   // channel_features[B,C,F]
                const float* __restrict__ Wih,  // [3F,F]
                const float* __restrict__ Whh,  // [3F,F]
                const float* __restrict__ bih,  // [3F]
                const float* __restrict__ bhh,  // [3F]
                const int*   __restrict__ ep,   // edge_path [E]
                float*       __restrict__ out)  // [B,C,F]
{
    // Weights as float4 quads: sW[fq][row] = W[row][4fq .. 4fq+3]
    __shared__ float4 sWih[8 * 96];
    __shared__ float4 sWhh[8 * 96];
    __shared__ float  sBias[128];
    // Per-channel staging (channel-in-CTA 0..7): x (agg) and h, layout [b][f]
    __shared__ __align__(16) float sA[CH_PER_CTA][256];
    __shared__ __align__(16) float sH[CH_PER_CTA][256];

    const int tid = threadIdx.x;

    for (int i = tid; i < 8 * 96; i += THREADS) {
        int fq = i / 96, row = i % 96;
        sWih[i] = __ldg((const float4*)(Wih + row * 32 + fq * 4));
        sWhh[i] = __ldg((const float4*)(Whh + row * 32 + fq * 4));
    }
    if (tid < 32) {
        sBias[tid]      = bih[tid]      + bhh[tid];       // r bias (combined)
        sBias[32 + tid] = bih[32 + tid] + bhh[32 + tid];  // z bias (combined)
        sBias[64 + tid] = bih[64 + tid];                  // n input bias
        sBias[96 + tid] = bhh[64 + tid];                  // n hidden bias (inside r*)
    }
    __syncthreads();

    const int w = tid >> 5, lane = tid & 31;
    const int p      = w >> 1;            // warp-pair 0..3
    const int parity = w & 1;             // batch half 0/1
    const int chA = 2 * p, chB = chA + 1; // channel-in-CTA
    const int cA  = blockIdx.x * CH_PER_CTA + chA;
    const int cB  = cA + 1;
    const int bb  = lane >> 3;            // 0..3
    const int q8  = lane & 7;             // 0..7
    const int gb  = parity * 4 + bb;      // global batch 0..7

    const float* pfL = pf + (size_t)gb * (P_DIM * F_DIM) + q8 * 4;

    // ---- gather channel A ----
    unsigned long long aA0 = 0ull, aA1 = 0ull;
    {
        const int s0 = g_offs[cA], e0 = g_offs[cA + 1];
        int i = s0;
        for (; i + 4 <= e0; i += 4) {
            int p0 = __ldg(ep + i + 0);
            int p1 = __ldg(ep + i + 1);
            int p2 = __ldg(ep + i + 2);
            int p3 = __ldg(ep + i + 3);
            ulonglong2 v0 = *(const ulonglong2*)(pfL + ((size_t)p0 << 5));
            ulonglong2 v1 = *(const ulonglong2*)(pfL + ((size_t)p1 << 5));
            ulonglong2 v2 = *(const ulonglong2*)(pfL + ((size_t)p2 << 5));
            ulonglong2 v3 = *(const ulonglong2*)(pfL + ((size_t)p3 << 5));
            aA0 = add2(aA0, v0.x); aA1 = add2(aA1, v0.y);
            aA0 = add2(aA0, v1.x); aA1 = add2(aA1, v1.y);
            aA0 = add2(aA0, v2.x); aA1 = add2(aA1, v2.y);
            aA0 = add2(aA0, v3.x); aA1 = add2(aA1, v3.y);
        }
        for (; i < e0; i++) {
            int pp = __ldg(ep + i);
            ulonglong2 v = *(const ulonglong2*)(pfL + ((size_t)pp << 5));
            aA0 = add2(aA0, v.x); aA1 = add2(aA1, v.y);
        }
    }
    // ---- gather channel B ----
    unsigned long long aB0 = 0ull, aB1 = 0ull;
    {
        const int s0 = g_offs[cB], e0 = g_offs[cB + 1];
        int i = s0;
        for (; i + 4 <= e0; i += 4) {
            int p0 = __ldg(ep + i + 0);
            int p1 = __ldg(ep + i + 1);
            int p2 = __ldg(ep + i + 2);
            int p3 = __ldg(ep + i + 3);
            ulonglong2 v0 = *(const ulonglong2*)(pfL + ((size_t)p0 << 5));
            ulonglong2 v1 = *(const ulonglong2*)(pfL + ((size_t)p1 << 5));
            ulonglong2 v2 = *(const ulonglong2*)(pfL + ((size_t)p2 << 5));
            ulonglong2 v3 = *(const ulonglong2*)(pfL + ((size_t)p3 << 5));
            aB0 = add2(aB0, v0.x); aB1 = add2(aB1, v0.y);
            aB0 = add2(aB0, v1.x); aB1 = add2(aB1, v1.y);
            aB0 = add2(aB0, v2.x); aB1 = add2(aB1, v2.y);
            aB0 = add2(aB0, v3.x); aB1 = add2(aB1, v3.y);
        }
        for (; i < e0; i++) {
            int pp = __ldg(ep + i);
            ulonglong2 v = *(const ulonglong2*)(pfL + ((size_t)pp << 5));
            aB0 = add2(aB0, v.x); aB1 = add2(aB1, v.y);
        }
    }

    // ---- stage x and h (vector STS/LDG, conflict-free) ----
    {
        ulonglong2 tA; tA.x = aA0; tA.y = aA1;
        ulonglong2 tB; tB.x = aB0; tB.y = aB1;
        *(ulonglong2*)&sA[chA][gb * 32 + q8 * 4] = tA;
        *(ulonglong2*)&sA[chB][gb * 32 + q8 * 4] = tB;
        const float* hA = hf + (size_t)gb * (C_DIM * F_DIM) + (size_t)cA * 32 + q8 * 4;
        ulonglong2 hvA = *(const ulonglong2*)hA;
        ulonglong2 hvB = *(const ulonglong2*)(hA + 32);  // cB = cA+1: next 128B row
        *(ulonglong2*)&sH[chA][gb * 32 + q8 * 4] = hvA;
        *(ulonglong2*)&sH[chB][gb * 32 + q8 * 4] = hvB;
    }
    __syncthreads();

    // ---- GEMM: lane j = output feature; 2 channels x 4 batches per warp ----
    const ulonglong2* WI = (const ulonglong2*)sWih;
    const ulonglong2* WH = (const ulonglong2*)sWhh;

    unsigned long long accr[2][4], accz[2][4], accxn[2][4], acchn[2][4];
#pragma unroll
    for (int cc = 0; cc < 2; cc++)
#pragma unroll
        for (int b = 0; b < 4; b++) {
            accr[cc][b] = 0ull; accz[cc][b] = 0ull;
            accxn[cc][b] = 0ull; acchn[cc][b] = 0ull;
        }

#pragma unroll
    for (int fq = 0; fq < 8; fq++) {
        ulonglong2 wir = WI[fq * 96 + lane];        // conflict-free LDS.128
        ulonglong2 wiz = WI[fq * 96 + 32 + lane];
        ulonglong2 win = WI[fq * 96 + 64 + lane];
        ulonglong2 whr = WH[fq * 96 + lane];
        ulonglong2 whz = WH[fq * 96 + 32 + lane];
        ulonglong2 whn = WH[fq * 96 + 64 + lane];
#pragma unroll
        for (int cc = 0; cc < 2; cc++) {
            const int ch = chA + cc;
#pragma unroll
            for (int b = 0; b < 4; b++) {
                const int row = (parity * 4 + b) * 32 + fq * 4;
                ulonglong2 a = *(const ulonglong2*)&sA[ch][row];  // broadcast
                ulonglong2 h = *(const ulonglong2*)&sH[ch][row];  // broadcast
                accr[cc][b]  = ffma2(a.y, wir.y, ffma2(a.x, wir.x, accr[cc][b]));
                accr[cc][b]  = ffma2(h.y, whr.y, ffma2(h.x, whr.x, accr[cc][b]));
                accz[cc][b]  = ffma2(a.y, wiz.y, ffma2(a.x, wiz.x, accz[cc][b]));
                accz[cc][b]  = ffma2(h.y, whz.y, ffma2(h.x, whz.x, accz[cc][b]));
                accxn[cc][b] = ffma2(a.y, win.y, ffma2(a.x, win.x, accxn[cc][b]));
                acchn[cc][b] = ffma2(h.y, whn.y, ffma2(h.x, whn.x, acchn[cc][b]));
            }
        }
    }

    // ---- gates + output (lane = feature) ----
    const float br  = sBias[lane];
    const float bz  = sBias[32 + lane];
    const float bxn = sBias[64 + lane];
    const float bhn = sBias[96 + lane];
#pragma unroll
    for (int cc = 0; cc < 2; cc++) {
        const int ch = chA + cc;
        const int c  = cA + cc;
        float* outp = out + ((size_t)c << 5) + lane;
#pragma unroll
        for (int b = 0; b < 4; b++) {
            const int gbb = parity * 4 + b;
            float r  = sigmoidf_fast(hadd2(accr[cc][b]) + br);
            float z  = sigmoidf_fast(hadd2(accz[cc][b]) + bz);
            float n  = tanhf_fast(hadd2(accxn[cc][b]) + bxn + r * (hadd2(acchn[cc][b]) + bhn));
            float hv = sH[ch][gbb * 32 + lane];
            outp[(size_t)gbb * (C_DIM * F_DIM)] = (1.0f - z) * n + z * hv;  // coalesced STG
        }
    }
}

extern "C" void kernel_launch(void* const* d_in, const int* in_sizes, int n_in,
                              void* d_out, int out_size) {
    (void)in_sizes; (void)n_in; (void)out_size;
    const float* pf  = (const float*)d_in[0];
    const float* hf  = (const float*)d_in[1];
    const float* Wih = (const float*)d_in[2];
    const float* Whh = (const float*)d_in[3];
    const float* bih = (const float*)d_in[4];
    const float* bhh = (const float*)d_in[5];
    const int*   ep  = (const int*)d_in[6];
    const int*   ec  = (const int*)d_in[7];
    float* out = (float*)d_out;

    offsets_kernel<<<(C_DIM + 1 + 255) / 256, 256>>>(ec);
    gru_kernel<<<C_DIM / CH_PER_CTA, THREADS>>>(pf, hf, Wih, Whh, bih, bhh, ep, out);
}

// round 13
// speedup vs baseline: 4.5975x; 1.3145x over previous
#include <cuda_runtime.h>
#include <cstdint>

// Problem constants (fixed shapes per reference)
#define B_DIM 8
#define P_DIM 65536
#define C_DIM 32768
#define F_DIM 32
#define E_DIM 524288

// Per-channel edge-range offsets (edge_channel is sorted)
__device__ int g_offs[C_DIM + 1];
// Gather scratch: agg[c][b*32+f]  (33.5 MB, mostly L2-resident)
__device__ __align__(16) float g_agg[(size_t)C_DIM * 256];

// ---------- packed f32x2 helpers ----------
__device__ __forceinline__ unsigned long long ffma2(unsigned long long a,
                                                    unsigned long long b,
                                                    unsigned long long c) {
    unsigned long long d;
    asm("fma.rn.f32x2 %0, %1, %2, %3;" : "=l"(d) : "l"(a), "l"(b), "l"(c));
    return d;
}
__device__ __forceinline__ unsigned long long add2(unsigned long long a,
                                                   unsigned long long b) {
    unsigned long long d;
    asm("add.rn.f32x2 %0, %1, %2;" : "=l"(d) : "l"(a), "l"(b));
    return d;
}
__device__ __forceinline__ float hadd2(unsigned long long v) {
    float lo, hi;
    asm("mov.b64 {%0, %1}, %2;" : "=f"(lo), "=f"(hi) : "l"(v));
    return lo + hi;
}
__device__ __forceinline__ float fast_rcp(float x) {
    float r;
    asm("rcp.approx.f32 %0, %1;" : "=f"(r) : "f"(x));
    return r;
}
__device__ __forceinline__ float sigmoidf_fast(float x) {
    return fast_rcp(1.0f + __expf(-x));
}
__device__ __forceinline__ float tanhf_fast(float x) {
    return fmaf(2.0f, sigmoidf_fast(2.0f * x), -1.0f);
}

// ---------- kernel 1: segment offsets via binary search ----------
__global__ void offsets_kernel(const int* __restrict__ ec) {
    int c = blockIdx.x * blockDim.x + threadIdx.x;
    if (c > C_DIM) return;
    int lo = 0, hi = E_DIM;
    while (lo < hi) {
        int mid = (lo + hi) >> 1;
        if (ec[mid] < c) lo = mid + 1; else hi = mid;
    }
    g_offs[c] = lo;  // lower_bound(edge_channel, c); c == C_DIM -> E_DIM
}

// ---------- kernel 2: gather only (high occupancy) ----------
// 128-thread CTA, one warp per channel. Lane = (bb = lane>>3, q8 = lane&7);
// instr A covers batches 0-3 (4 x 128B rows), instr B batches 4-7.
// No GEMM state -> ~70 regs -> 7 CTAs = 28 warps/SM of latency cover.
__global__ __launch_bounds__(128, 7)
void gather_kernel(const float* __restrict__ pf,  // path_features [B,P,F]
                   const int*   __restrict__ ep)  // edge_path [E]
{
    const int w = threadIdx.x >> 5, lane = threadIdx.x & 31;
    const int c  = blockIdx.x * 4 + w;
    const int bb = lane >> 3;        // batch 0..3 (and bb+4 for second half)
    const int q8 = lane & 7;         // feature quad 0..7

    unsigned long long aA0 = 0ull, aA1 = 0ull;   // batch bb
    unsigned long long aB0 = 0ull, aB1 = 0ull;   // batch bb+4
    const float* pfA = pf + (size_t)bb * (P_DIM * F_DIM) + q8 * 4;
    const float* pfB = pfA + (size_t)4 * (P_DIM * F_DIM);

    const int s0 = g_offs[c], e0 = g_offs[c + 1];
    int i = s0;
    for (; i + 8 <= e0; i += 8) {
        int p0 = __ldg(ep + i + 0);
        int p1 = __ldg(ep + i + 1);
        int p2 = __ldg(ep + i + 2);
        int p3 = __ldg(ep + i + 3);
        int p4 = __ldg(ep + i + 4);
        int p5 = __ldg(ep + i + 5);
        int p6 = __ldg(ep + i + 6);
        int p7 = __ldg(ep + i + 7);
        ulonglong2 vA0 = *(const ulonglong2*)(pfA + ((size_t)p0 << 5));
        ulonglong2 vB0 = *(const ulonglong2*)(pfB + ((size_t)p0 << 5));
        ulonglong2 vA1 = *(const ulonglong2*)(pfA + ((size_t)p1 << 5));
        ulonglong2 vB1 = *(const ulonglong2*)(pfB + ((size_t)p1 << 5));
        ulonglong2 vA2 = *(const ulonglong2*)(pfA + ((size_t)p2 << 5));
        ulonglong2 vB2 = *(const ulonglong2*)(pfB + ((size_t)p2 << 5));
        ulonglong2 vA3 = *(const ulonglong2*)(pfA + ((size_t)p3 << 5));
        ulonglong2 vB3 = *(const ulonglong2*)(pfB + ((size_t)p3 << 5));
        ulonglong2 vA4 = *(const ulonglong2*)(pfA + ((size_t)p4 << 5));
        ulonglong2 vB4 = *(const ulonglong2*)(pfB + ((size_t)p4 << 5));
        ulonglong2 vA5 = *(const ulonglong2*)(pfA + ((size_t)p5 << 5));
        ulonglong2 vB5 = *(const ulonglong2*)(pfB + ((size_t)p5 << 5));
        ulonglong2 vA6 = *(const ulonglong2*)(pfA + ((size_t)p6 << 5));
        ulonglong2 vB6 = *(const ulonglong2*)(pfB + ((size_t)p6 << 5));
        ulonglong2 vA7 = *(const ulonglong2*)(pfA + ((size_t)p7 << 5));
        ulonglong2 vB7 = *(const ulonglong2*)(pfB + ((size_t)p7 << 5));
        aA0 = add2(aA0, vA0.x); aA1 = add2(aA1, vA0.y);
        aB0 = add2(aB0, vB0.x); aB1 = add2(aB1, vB0.y);
        aA0 = add2(aA0, vA1.x); aA1 = add2(aA1, vA1.y);
        aB0 = add2(aB0, vB1.x); aB1 = add2(aB1, vB1.y);
        aA0 = add2(aA0, vA2.x); aA1 = add2(aA1, vA2.y);
        aB0 = add2(aB0, vB2.x); aB1 = add2(aB1, vB2.y);
        aA0 = add2(aA0, vA3.x); aA1 = add2(aA1, vA3.y);
        aB0 = add2(aB0, vB3.x); aB1 = add2(aB1, vB3.y);
        aA0 = add2(aA0, vA4.x); aA1 = add2(aA1, vA4.y);
        aB0 = add2(aB0, vB4.x); aB1 = add2(aB1, vB4.y);
        aA0 = add2(aA0, vA5.x); aA1 = add2(aA1, vA5.y);
        aB0 = add2(aB0, vB5.x); aB1 = add2(aB1, vB5.y);
        aA0 = add2(aA0, vA6.x); aA1 = add2(aA1, vA6.y);
        aB0 = add2(aB0, vB6.x); aB1 = add2(aB1, vB6.y);
        aA0 = add2(aA0, vA7.x); aA1 = add2(aA1, vA7.y);
        aB0 = add2(aB0, vB7.x); aB1 = add2(aB1, vB7.y);
    }
    for (; i < e0; i++) {
        int p = __ldg(ep + i);
        ulonglong2 vA = *(const ulonglong2*)(pfA + ((size_t)p << 5));
        ulonglong2 vB = *(const ulonglong2*)(pfB + ((size_t)p << 5));
        aA0 = add2(aA0, vA.x); aA1 = add2(aA1, vA.y);
        aB0 = add2(aB0, vB.x); aB1 = add2(aB1, vB.y);
    }

    // Coalesced STG.128 to scratch: agg[c][b*32 + f]
    float* dst = g_agg + (size_t)c * 256;
    ulonglong2 tA; tA.x = aA0; tA.y = aA1;
    ulonglong2 tB; tB.x = aB0; tB.y = aB1;
    *(ulonglong2*)(dst + bb * 32 + q8 * 4)       = tA;
    *(ulonglong2*)(dst + (bb + 4) * 32 + q8 * 4) = tB;
}

// ---------- kernel 3: GRU (dense compute, R7 GEMM structure) ----------
// 256-thread CTA, one warp per channel; lane = output feature j.
__global__ __launch_bounds__(256, 2)
void gru_kernel(const float* __restrict__ hf,   // channel_features[B,C,F]
                const float* __restrict__ Wih,  // [3F,F]
                const float* __restrict__ Whh,  // [3F,F]
                const float* __restrict__ bih,  // [3F]
                const float* __restrict__ bhh,  // [3F]
                float*       __restrict__ out)  // [B,C,F]
{
    __shared__ float4 sWih[8 * 96];
    __shared__ float4 sWhh[8 * 96];
    __shared__ float  sBias[128];
    __shared__ __align__(16) float sA[8][256];
    __shared__ __align__(16) float sH[8][256];

    const int tid = threadIdx.x;

    for (int i = tid; i < 8 * 96; i += 256) {
        int fq = i / 96, row = i % 96;
        sWih[i] = __ldg((const float4*)(Wih + row * 32 + fq * 4));
        sWhh[i] = __ldg((const float4*)(Whh + row * 32 + fq * 4));
    }
    if (tid < 32) {
        sBias[tid]      = bih[tid]      + bhh[tid];       // r bias (combined)
        sBias[32 + tid] = bih[32 + tid] + bhh[32 + tid];  // z bias (combined)
        sBias[64 + tid] = bih[64 + tid];                  // n input bias
        sBias[96 + tid] = bhh[64 + tid];                  // n hidden bias (inside r*)
    }
    __syncthreads();

    const int w = tid >> 5, lane = tid & 31;
    const int c  = blockIdx.x * 8 + w;
    const int bb = lane >> 3, q8 = lane & 7;

    // Stage x (from scratch) and h (from hf) into per-warp shared
    {
        const float* src = g_agg + (size_t)c * 256;
        ulonglong2 xA = *(const ulonglong2*)(src + bb * 32 + q8 * 4);
        ulonglong2 xB = *(const ulonglong2*)(src + (bb + 4) * 32 + q8 * 4);
        *(ulonglong2*)&sA[w][bb * 32 + q8 * 4]       = xA;
        *(ulonglong2*)&sA[w][(bb + 4) * 32 + q8 * 4] = xB;
        const float* hA = hf + (size_t)bb * (C_DIM * F_DIM) + ((size_t)c << 5) + q8 * 4;
        const float* hB = hA + (size_t)4 * (C_DIM * F_DIM);
        ulonglong2 hvA = *(const ulonglong2*)hA;
        ulonglong2 hvB = *(const ulonglong2*)hB;
        *(ulonglong2*)&sH[w][bb * 32 + q8 * 4]       = hvA;
        *(ulonglong2*)&sH[w][(bb + 4) * 32 + q8 * 4] = hvB;
    }
    __syncwarp();

    const ulonglong2* WI = (const ulonglong2*)sWih;
    const ulonglong2* WH = (const ulonglong2*)sWhh;

    unsigned long long accr[B_DIM], accz[B_DIM], accxn[B_DIM], acchn[B_DIM];
#pragma unroll
    for (int b = 0; b < B_DIM; b++) { accr[b] = 0ull; accz[b] = 0ull; accxn[b] = 0ull; acchn[b] = 0ull; }

#pragma unroll
    for (int fq = 0; fq < 8; fq++) {
        ulonglong2 wir = WI[fq * 96 + lane];        // conflict-free LDS.128
        ulonglong2 wiz = WI[fq * 96 + 32 + lane];
        ulonglong2 win = WI[fq * 96 + 64 + lane];
        ulonglong2 whr = WH[fq * 96 + lane];
        ulonglong2 whz = WH[fq * 96 + 32 + lane];
        ulonglong2 whn = WH[fq * 96 + 64 + lane];
#pragma unroll
        for (int b = 0; b < B_DIM; b++) {
            ulonglong2 a = *(const ulonglong2*)&sA[w][b * 32 + fq * 4];  // broadcast
            ulonglong2 h = *(const ulonglong2*)&sH[w][b * 32 + fq * 4];  // broadcast
            accr[b]  = ffma2(a.y, wir.y, ffma2(a.x, wir.x, accr[b]));
            accr[b]  = ffma2(h.y, whr.y, ffma2(h.x, whr.x, accr[b]));
            accz[b]  = ffma2(a.y, wiz.y, ffma2(a.x, wiz.x, accz[b]));
            accz[b]  = ffma2(h.y, whz.y, ffma2(h.x, whz.x, accz[b]));
            accxn[b] = ffma2(a.y, win.y, ffma2(a.x, win.x, accxn[b]));
            acchn[b] = ffma2(h.y, whn.y, ffma2(h.x, whn.x, acchn[b]));
        }
    }

    const float br  = sBias[lane];
    const float bz  = sBias[32 + lane];
    const float bxn = sBias[64 + lane];
    const float bhn = sBias[96 + lane];
    float* outp = out + ((size_t)c << 5) + lane;
#pragma unroll
    for (int b = 0; b < B_DIM; b++) {
        float r  = sigmoidf_fast(hadd2(accr[b]) + br);
        float z  = sigmoidf_fast(hadd2(accz[b]) + bz);
        float n  = tanhf_fast(hadd2(accxn[b]) + bxn + r * (hadd2(acchn[b]) + bhn));
        float hv = sH[w][b * 32 + lane];
        outp[(size_t)b * (C_DIM * F_DIM)] = (1.0f - z) * n + z * hv;  // coalesced STG
    }
}

extern "C" void kernel_launch(void* const* d_in, const int* in_sizes, int n_in,
                              void* d_out, int out_size) {
    (void)in_sizes; (void)n_in; (void)out_size;
    const float* pf  = (const float*)d_in[0];
    const float* hf  = (const float*)d_in[1];
    const float* Wih = (const float*)d_in[2];
    const float* Whh = (const float*)d_in[3];
    const float* bih = (const float*)d_in[4];
    const float* bhh = (const float*)d_in[5];
    const int*   ep  = (const int*)d_in[6];
    const int*   ec  = (const int*)d_in[7];
    float* out = (float*)d_out;

    offsets_kernel<<<(C_DIM + 1 + 255) / 256, 256>>>(ec);
    gather_kernel<<<C_DIM / 4, 128>>>(pf, ep);
    gru_kernel<<<C_DIM / 8, 256>>>(hf, Wih, Whh, bih, bhh, out);
}

// round 15
// speedup vs baseline: 4.8923x; 1.0641x over previous
#include <cuda_runtime.h>
#include <cstdint>

// Problem constants (fixed shapes per reference)
#define B_DIM 8
#define P_DIM 65536
#define C_DIM 32768
#define F_DIM 32
#define E_DIM 524288

// Per-channel edge-range offsets (edge_channel is sorted)
__device__ int g_offs[C_DIM + 1];
// Gather scratch: agg[c][b*32+f]  (33.5 MB, mostly L2-resident)
__device__ __align__(16) float g_agg[(size_t)C_DIM * 256];

// ---------- packed f32x2 helpers ----------
__device__ __forceinline__ unsigned long long ffma2(unsigned long long a,
                                                    unsigned long long b,
                                                    unsigned long long c) {
    unsigned long long d;
    asm("fma.rn.f32x2 %0, %1, %2, %3;" : "=l"(d) : "l"(a), "l"(b), "l"(c));
    return d;
}
__device__ __forceinline__ unsigned long long add2(unsigned long long a,
                                                   unsigned long long b) {
    unsigned long long d;
    asm("add.rn.f32x2 %0, %1, %2;" : "=l"(d) : "l"(a), "l"(b));
    return d;
}
__device__ __forceinline__ float hadd2(unsigned long long v) {
    float lo, hi;
    asm("mov.b64 {%0, %1}, %2;" : "=f"(lo), "=f"(hi) : "l"(v));
    return lo + hi;
}
__device__ __forceinline__ float fast_rcp(float x) {
    float r;
    asm("rcp.approx.f32 %0, %1;" : "=f"(r) : "f"(x));
    return r;
}
__device__ __forceinline__ float sigmoidf_fast(float x) {
    return fast_rcp(1.0f + __expf(-x));
}
__device__ __forceinline__ float tanhf_fast(float x) {
    return fmaf(2.0f, sigmoidf_fast(2.0f * x), -1.0f);
}

// ---------- kernel 1: segment offsets via boundary scatter ----------
// One thread per edge; thread i fills offs[c] = i for all c in (ec[i-1], ec[i]].
// Coalesced reads, O(gap) scatter writes, no dependent-load chains.
__global__ void offsets_kernel(const int* __restrict__ ec) {
    int i = blockIdx.x * blockDim.x + threadIdx.x;
    if (i >= E_DIM) return;
    int cur  = __ldg(ec + i);
    int prev = (i == 0) ? -1 : __ldg(ec + i - 1);
    for (int c = prev + 1; c <= cur; c++) g_offs[c] = i;  // lower_bound(ec, c) = i
    if (i == E_DIM - 1) {
        for (int c = cur + 1; c <= C_DIM; c++) g_offs[c] = E_DIM;
    }
}

// ---------- kernel 2: gather only (high occupancy) ----------
// 128-thread CTA, one warp per channel. Lane = (bb = lane>>3, q8 = lane&7);
// instr A covers batches 0-3 (4 x 128B rows), instr B batches 4-7.
// No GEMM state -> ~70 regs -> 7 CTAs = 28 warps/SM of latency cover.
__global__ __launch_bounds__(128, 7)
void gather_kernel(const float* __restrict__ pf,  // path_features [B,P,F]
                   const int*   __restrict__ ep)  // edge_path [E]
{
    const int w = threadIdx.x >> 5, lane = threadIdx.x & 31;
    const int c  = blockIdx.x * 4 + w;
    const int bb = lane >> 3;        // batch 0..3 (and bb+4 for second half)
    const int q8 = lane & 7;         // feature quad 0..7

    unsigned long long aA0 = 0ull, aA1 = 0ull;   // batch bb
    unsigned long long aB0 = 0ull, aB1 = 0ull;   // batch bb+4
    const float* pfA = pf + (size_t)bb * (P_DIM * F_DIM) + q8 * 4;
    const float* pfB = pfA + (size_t)4 * (P_DIM * F_DIM);

    const int s0 = g_offs[c], e0 = g_offs[c + 1];
    int i = s0;
    for (; i + 8 <= e0; i += 8) {
        int p0 = __ldg(ep + i + 0);
        int p1 = __ldg(ep + i + 1);
        int p2 = __ldg(ep + i + 2);
        int p3 = __ldg(ep + i + 3);
        int p4 = __ldg(ep + i + 4);
        int p5 = __ldg(ep + i + 5);
        int p6 = __ldg(ep + i + 6);
        int p7 = __ldg(ep + i + 7);
        ulonglong2 vA0 = *(const ulonglong2*)(pfA + ((size_t)p0 << 5));
        ulonglong2 vB0 = *(const ulonglong2*)(pfB + ((size_t)p0 << 5));
        ulonglong2 vA1 = *(const ulonglong2*)(pfA + ((size_t)p1 << 5));
        ulonglong2 vB1 = *(const ulonglong2*)(pfB + ((size_t)p1 << 5));
        ulonglong2 vA2 = *(const ulonglong2*)(pfA + ((size_t)p2 << 5));
        ulonglong2 vB2 = *(const ulonglong2*)(pfB + ((size_t)p2 << 5));
        ulonglong2 vA3 = *(const ulonglong2*)(pfA + ((size_t)p3 << 5));
        ulonglong2 vB3 = *(const ulonglong2*)(pfB + ((size_t)p3 << 5));
        ulonglong2 vA4 = *(const ulonglong2*)(pfA + ((size_t)p4 << 5));
        ulonglong2 vB4 = *(const ulonglong2*)(pfB + ((size_t)p4 << 5));
        ulonglong2 vA5 = *(const ulonglong2*)(pfA + ((size_t)p5 << 5));
        ulonglong2 vB5 = *(const ulonglong2*)(pfB + ((size_t)p5 << 5));
        ulonglong2 vA6 = *(const ulonglong2*)(pfA + ((size_t)p6 << 5));
        ulonglong2 vB6 = *(const ulonglong2*)(pfB + ((size_t)p6 << 5));
        ulonglong2 vA7 = *(const ulonglong2*)(pfA + ((size_t)p7 << 5));
        ulonglong2 vB7 = *(const ulonglong2*)(pfB + ((size_t)p7 << 5));
        aA0 = add2(aA0, vA0.x); aA1 = add2(aA1, vA0.y);
        aB0 = add2(aB0, vB0.x); aB1 = add2(aB1, vB0.y);
        aA0 = add2(aA0, vA1.x); aA1 = add2(aA1, vA1.y);
        aB0 = add2(aB0, vB1.x); aB1 = add2(aB1, vB1.y);
        aA0 = add2(aA0, vA2.x); aA1 = add2(aA1, vA2.y);
        aB0 = add2(aB0, vB2.x); aB1 = add2(aB1, vB2.y);
        aA0 = add2(aA0, vA3.x); aA1 = add2(aA1, vA3.y);
        aB0 = add2(aB0, vB3.x); aB1 = add2(aB1, vB3.y);
        aA0 = add2(aA0, vA4.x); aA1 = add2(aA1, vA4.y);
        aB0 = add2(aB0, vB4.x); aB1 = add2(aB1, vB4.y);
        aA0 = add2(aA0, vA5.x); aA1 = add2(aA1, vA5.y);
        aB0 = add2(aB0, vB5.x); aB1 = add2(aB1, vB5.y);
        aA0 = add2(aA0, vA6.x); aA1 = add2(aA1, vA6.y);
        aB0 = add2(aB0, vB6.x); aB1 = add2(aB1, vB6.y);
        aA0 = add2(aA0, vA7.x); aA1 = add2(aA1, vA7.y);
        aB0 = add2(aB0, vB7.x); aB1 = add2(aB1, vB7.y);
    }
    for (; i < e0; i++) {
        int p = __ldg(ep + i);
        ulonglong2 vA = *(const ulonglong2*)(pfA + ((size_t)p << 5));
        ulonglong2 vB = *(const ulonglong2*)(pfB + ((size_t)p << 5));
        aA0 = add2(aA0, vA.x); aA1 = add2(aA1, vA.y);
        aB0 = add2(aB0, vB.x); aB1 = add2(aB1, vB.y);
    }

    // Coalesced STG.128 to scratch: agg[c][b*32 + f]
    float* dst = g_agg + (size_t)c * 256;
    ulonglong2 tA; tA.x = aA0; tA.y = aA1;
    ulonglong2 tB; tB.x = aB0; tB.y = aB1;
    *(ulonglong2*)(dst + bb * 32 + q8 * 4)       = tA;
    *(ulonglong2*)(dst + (bb + 4) * 32 + q8 * 4) = tB;
}

// ---------- kernel 3: GRU (warp-pair GEMM: 2 channels x 4 batches/warp) ----------
// 256-thread CTA = 8 warps = 4 warp-pairs, 8 channels per CTA. Staging is
// per-warp (warp w stages channel w); GEMM uses pair p = w>>1 on channels
// {2p, 2p+1} with parity = w&1 selecting batches [4*parity, 4*parity+4).
// Weight LDS amortized over 2 channels; accumulators 2x4x4 = 32 u64 (same
// register budget as R7/R13: ~126 regs, 2 CTAs/SM, no spill).
__global__ __launch_bounds__(256, 2)
void gru_kernel(const float* __restrict__ hf,   // channel_features[B,C,F]
                const float* __restrict__ Wih,  // [3F,F]
                const float* __restrict__ Whh,  // [3F,F]
                const float* __restrict__ bih,  // [3F]
                const float* __restrict__ bhh,  // [3F]
                float*       __restrict__ out)  // [B,C,F]
{
    __shared__ float4 sWih[8 * 96];
    __shared__ float4 sWhh[8 * 96];
    __shared__ float  sBias[128];
    __shared__ __align__(16) float sA[8][256];
    __shared__ __align__(16) float sH[8][256];

    const int tid = threadIdx.x;

    for (int i = tid; i < 8 * 96; i += 256) {
        int fq = i / 96, row = i % 96;
        sWih[i] = __ldg((const float4*)(Wih + row * 32 + fq * 4));
        sWhh[i] = __ldg((const float4*)(Whh + row * 32 + fq * 4));
    }
    if (tid < 32) {
        sBias[tid]      = bih[tid]      + bhh[tid];       // r bias (combined)
        sBias[32 + tid] = bih[32 + tid] + bhh[32 + tid];  // z bias (combined)
        sBias[64 + tid] = bih[64 + tid];                  // n input bias
        sBias[96 + tid] = bhh[64 + tid];                  // n hidden bias (inside r*)
    }

    const int w = tid >> 5, lane = tid & 31;
    const int bb = lane >> 3, q8 = lane & 7;

    // ---- stage: warp w stages channel (CTA base + w) from scratch + hf ----
    {
        const int c = blockIdx.x * 8 + w;
        const float* src = g_agg + (size_t)c * 256;
        ulonglong2 xA = *(const ulonglong2*)(src + bb * 32 + q8 * 4);
        ulonglong2 xB = *(const ulonglong2*)(src + (bb + 4) * 32 + q8 * 4);
        *(ulonglong2*)&sA[w][bb * 32 + q8 * 4]       = xA;
        *(ulonglong2*)&sA[w][(bb + 4) * 32 + q8 * 4] = xB;
        const float* hA = hf + (size_t)bb * (C_DIM * F_DIM) + ((size_t)c << 5) + q8 * 4;
        const float* hB = hA + (size_t)4 * (C_DIM * F_DIM);
        ulonglong2 hvA = *(const ulonglong2*)hA;
        ulonglong2 hvB = *(const ulonglong2*)hB;
        *(ulonglong2*)&sH[w][bb * 32 + q8 * 4]       = hvA;
        *(ulonglong2*)&sH[w][(bb + 4) * 32 + q8 * 4] = hvB;
    }
    __syncthreads();

    // ---- GEMM: warp-pair p owns channels {2p, 2p+1}; parity = batch half ----
    const int p      = w >> 1;
    const int parity = w & 1;
    const int chA = 2 * p;                 // channel-in-CTA
    const ulonglong2* WI = (const ulonglong2*)sWih;
    const ulonglong2* WH = (const ulonglong2*)sWhh;

    unsigned long long accr[2][4], accz[2][4], accxn[2][4], acchn[2][4];
#pragma unroll
    for (int cc = 0; cc < 2; cc++)
#pragma unroll
        for (int b = 0; b < 4; b++) {
            accr[cc][b] = 0ull; accz[cc][b] = 0ull;
            accxn[cc][b] = 0ull; acchn[cc][b] = 0ull;
        }

#pragma unroll
    for (int fq = 0; fq < 8; fq++) {
        ulonglong2 wir = WI[fq * 96 + lane];        // conflict-free LDS.128
        ulonglong2 wiz = WI[fq * 96 + 32 + lane];
        ulonglong2 win = WI[fq * 96 + 64 + lane];
        ulonglong2 whr = WH[fq * 96 + lane];
        ulonglong2 whz = WH[fq * 96 + 32 + lane];
        ulonglong2 whn = WH[fq * 96 + 64 + lane];
#pragma unroll
        for (int cc = 0; cc < 2; cc++) {
            const int ch = chA + cc;
#pragma unroll
            for (int b = 0; b < 4; b++) {
                const int row = (parity * 4 + b) * 32 + fq * 4;
                ulonglong2 a = *(const ulonglong2*)&sA[ch][row];  // broadcast
                ulonglong2 h = *(const ulonglong2*)&sH[ch][row];  // broadcast
                accr[cc][b]  = ffma2(a.y, wir.y, ffma2(a.x, wir.x, accr[cc][b]));
                accr[cc][b]  = ffma2(h.y, whr.y, ffma2(h.x, whr.x, accr[cc][b]));
                accz[cc][b]  = ffma2(a.y, wiz.y, ffma2(a.x, wiz.x, accz[cc][b]));
                accz[cc][b]  = ffma2(h.y, whz.y, ffma2(h.x, whz.x, accz[cc][b]));
                accxn[cc][b] = ffma2(a.y, win.y, ffma2(a.x, win.x, accxn[cc][b]));
                acchn[cc][b] = ffma2(h.y, whn.y, ffma2(h.x, whn.x, acchn[cc][b]));
            }
        }
    }

    // ---- gates + output (lane = feature) ----
    const float br  = sBias[lane];
    const float bz  = sBias[32 + lane];
    const float bxn = sBias[64 + lane];
    const float bhn = sBias[96 + lane];
#pragma unroll
    for (int cc = 0; cc < 2; cc++) {
        const int ch = chA + cc;
        const int c  = blockIdx.x * 8 + ch;
        float* outp = out + ((size_t)c << 5) + lane;
#pragma unroll
        for (int b = 0; b < 4; b++) {
            const int gb = parity * 4 + b;
            float r  = sigmoidf_fast(hadd2(accr[cc][b]) + br);
            float z  = sigmoidf_fast(hadd2(accz[cc][b]) + bz);
            float n  = tanhf_fast(hadd2(accxn[cc][b]) + bxn + r * (hadd2(acchn[cc][b]) + bhn));
            float hv = sH[ch][gb * 32 + lane];
            outp[(size_t)gb * (C_DIM * F_DIM)] = (1.0f - z) * n + z * hv;  // coalesced STG
        }
    }
}

extern "C" void kernel_launch(void* const* d_in, const int* in_sizes, int n_in,
                              void* d_out, int out_size) {
    (void)in_sizes; (void)n_in; (void)out_size;
    const float* pf  = (const float*)d_in[0];
    const float* hf  = (const float*)d_in[1];
    const float* Wih = (const float*)d_in[2];
    const float* Whh = (const float*)d_in[3];
    const float* bih = (const float*)d_in[4];
    const float* bhh = (const float*)d_in[5];
    const int*   ep  = (const int*)d_in[6];
    const int*   ec  = (const int*)d_in[7];
    float* out = (float*)d_out;

    offsets_kernel<<<E_DIM / 256, 256>>>(ec);
    gather_kernel<<<C_DIM / 4, 128>>>(pf, ep);
    gru_kernel<<<C_DIM / 8, 256>>>(hf, Wih, Whh, bih, bhh, out);
}